// round 13
// baseline (speedup 1.0000x reference)
#include <cuda_runtime.h>

#define NROWS  8192
#define DCOLS  4096
#define MARGINF 5.0f
#define MAXLIST 2048
#define DTHREADS 256

// Scratch. Initial values match the post-run reset done by the last block,
// so every graph replay starts from identical state.
__device__ float        g_d[NROWS];
__device__ double       g_sp = 0.0;             // sum of pos distances
__device__ double       g_sn = 0.0;             // sum of neg distances
__device__ int          g_np = 0;               // pos count
__device__ int          g_minpos = 0x7f800000;  // +inf bits (pos-float ordering)
__device__ int          g_maxneg = 0;           // 0.0f bits
__device__ unsigned int g_ticket = 0u;

// One block per row: d = sqrt(sum (recon-x)^2) + 0.001 with fused global
// stats atomics (fire-and-forget REDG). Block completion is published with
// a RELEASE atomic on the ticket (no MEMBAR -> no chip-wide LSU throttle).
// The LAST block acquires and finalizes:
//   Sum_{i pos, j neg} max(0, d_i - d_j + M)
// = [Nn*Sp - Np*Sn + M*Np*Nn] + Sum max(0, d_j - d_i - M)
// Correction candidates: pos with d_i < max_neg - M, neg with d_j > min_pos + M
// (~330 each expected); exact cross product, pos-striped across threads.
__global__ __launch_bounds__(DTHREADS) void dist_kernel(
    const float* __restrict__ recon, const float* __restrict__ x,
    const int* __restrict__ targets, float* __restrict__ out)
{
    const int row = blockIdx.x;
    const int tid = threadIdx.x;
    const float4* r4 = reinterpret_cast<const float4*>(recon + (size_t)row * DCOLS);
    const float4* x4 = reinterpret_cast<const float4*>(x + (size_t)row * DCOLS);

    float acc = 0.0f;
    #pragma unroll 4
    for (int k = tid; k < DCOLS / 4; k += DTHREADS) {
        float4 a = r4[k];
        float4 b = x4[k];
        float d0 = a.x - b.x;
        float d1 = a.y - b.y;
        float d2 = a.z - b.z;
        float d3 = a.w - b.w;
        acc = fmaf(d0, d0, acc);
        acc = fmaf(d1, d1, acc);
        acc = fmaf(d2, d2, acc);
        acc = fmaf(d3, d3, acc);
    }

    #pragma unroll
    for (int o = 16; o > 0; o >>= 1)
        acc += __shfl_xor_sync(0xFFFFFFFFu, acc, o);

    __shared__ float ws[8];
    __shared__ int   s_last;
    if ((tid & 31) == 0) ws[tid >> 5] = acc;
    __syncthreads();

    if (tid == 0) {
        float s = 0.0f;
        #pragma unroll
        for (int w = 0; w < 8; w++) s += ws[w];
        float d = sqrtf(s) + 0.001f;
        g_d[row] = d;
        int bits = __float_as_int(d);   // positive floats: int order == float order
        if (targets[row] == 1) {
            atomicAdd(&g_sp, (double)d);   // no return use -> REDG fire-and-forget
            atomicMin(&g_minpos, bits);
            atomicAdd(&g_np, 1);
        } else {
            atomicAdd(&g_sn, (double)d);
            atomicMax(&g_maxneg, bits);
        }
        // Release-ordered ticket: publishes all prior writes without MEMBAR.
        unsigned int one = 1u, t;
        asm volatile("atom.release.gpu.global.add.u32 %0, [%1], %2;"
                     : "=r"(t) : "l"(&g_ticket), "r"(one) : "memory");
        s_last = (t == NROWS - 1);
    }
    __syncthreads();
    if (!s_last) return;

    // ================= last block: fused finalize =================
    // Acquire: make all released writes (g_d, stats) visible to this block.
    asm volatile("fence.acq_rel.gpu;" ::: "memory");

    __shared__ float  posList[MAXLIST], negList[MAXLIST];
    __shared__ int    s_npl, s_nnl;
    __shared__ double redC[8];

    if (tid == 0) { s_npl = 0; s_nnl = 0; }
    __syncthreads();

    const float minpos = __int_as_float(g_minpos);
    const float maxneg = __int_as_float(g_maxneg);
    const float thrP = maxneg - MARGINF;   // pos matter if d_i < thrP
    const float thrN = minpos + MARGINF;   // neg matter if d_j > thrN

    // Scan (all data L2-hot): gather hinge-overflow candidates
    for (int k = tid; k < NROWS; k += DTHREADS) {
        int   t  = targets[k];
        float dv = g_d[k];
        if (t == 1) {
            if (dv < thrP) {
                int idx = atomicAdd(&s_npl, 1);
                if (idx < MAXLIST) posList[idx] = dv;
            }
        } else {
            if (dv > thrN) {
                int idx = atomicAdd(&s_nnl, 1);
                if (idx < MAXLIST) negList[idx] = dv;
            }
        }
    }
    __syncthreads();

    const int npl = min(s_npl, MAXLIST);
    const int nnl = min(s_nnl, MAXLIST);

    // Exact correction: pos-striped, neg list serial per pos
    float corrF = 0.0f;
    for (int ip = tid; ip < npl; ip += DTHREADS) {
        const float dp = posList[ip] + MARGINF;
        float a = 0.0f;
        for (int jn = 0; jn < nnl; jn++) {
            a += fmaxf(negList[jn] - dp, 0.0f);
        }
        corrF += a;
    }
    double corr = (double)corrF;
    #pragma unroll
    for (int o = 16; o > 0; o >>= 1)
        corr += __shfl_xor_sync(0xFFFFFFFFu, corr, o);
    if ((tid & 31) == 0) redC[tid >> 5] = corr;
    __syncthreads();

    if (tid == 0) {
        double c = 0.0;
        #pragma unroll
        for (int w = 0; w < 8; w++) c += redC[w];
        double Sp = g_sp, Sn = g_sn;
        int    p  = g_np;
        double Np = (double)p;
        double Nn = (double)(NROWS - p);
        double linear = Nn * Sp - Np * Sn + (double)MARGINF * Np * Nn;
        out[0] = (float)((linear + c) / (Np * Nn));
        // reset for next graph replay
        g_sp = 0.0;
        g_sn = 0.0;
        g_np = 0;
        g_minpos = 0x7f800000;
        g_maxneg = 0;
        g_ticket = 0u;
    }
}

extern "C" void kernel_launch(void* const* d_in, const int* in_sizes, int n_in,
                              void* d_out, int out_size)
{
    const float* recon   = (const float*)d_in[0];
    const float* x       = (const float*)d_in[1];
    const int*   targets = (const int*)d_in[2];
    float* out = (float*)d_out;

    dist_kernel<<<NROWS, DTHREADS>>>(recon, x, targets, out);
}

// round 14
// speedup vs baseline: 1.0303x; 1.0303x over previous
#include <cuda_runtime.h>

#define NROWS  8192
#define DCOLS  4096
#define MARGINF 5.0f
#define MAXLIST 2048
#define DTHREADS 256
#define RPB 8                       // rows per block (one per warp)
#define NBLOCKS (NROWS / RPB)       // 1024

// Scratch. Initial values match the post-run reset done by the last block,
// so every graph replay starts from identical state.
__device__ float        g_d[NROWS];
__device__ double       g_sp = 0.0;             // sum of pos distances
__device__ double       g_sn = 0.0;             // sum of neg distances
__device__ int          g_np = 0;               // pos count
__device__ int          g_minpos = 0x7f800000;  // +inf bits (pos-float ordering)
__device__ int          g_maxneg = 0;           // 0.0f bits
__device__ unsigned int g_ticket = 0u;

// Warp-per-row distance kernel with fused stats + last-block finalize.
// Each warp privately reduces one row (no intra-mainloop syncs, stats via
// fire-and-forget REDG). ONE blocking ticket per block (amortized over 8
// rows of HBM work) keeps resident-block turnover off the critical path.
// Last block:  Sum_{i pos, j neg} max(0, d_i-d_j+M)
//   = [Nn*Sp - Np*Sn + M*Np*Nn] + Sum max(0, d_j - d_i - M)
// Correction candidates: pos with d_i < max_neg-M, neg with d_j > min_pos+M
// (~330 each); exact cross product, pos-striped across threads.
__global__ __launch_bounds__(DTHREADS) void dist_kernel(
    const float* __restrict__ recon, const float* __restrict__ x,
    const int* __restrict__ targets, float* __restrict__ out)
{
    const int tid  = threadIdx.x;
    const int lane = tid & 31;
    const int wid  = tid >> 5;
    const int row  = blockIdx.x * RPB + wid;

    const float4* r4 = reinterpret_cast<const float4*>(recon + (size_t)row * DCOLS);
    const float4* x4 = reinterpret_cast<const float4*>(x + (size_t)row * DCOLS);

    float acc = 0.0f;
    #pragma unroll 8
    for (int k = lane; k < DCOLS / 4; k += 32) {   // 32 iters, 512B/warp-load
        float4 a = r4[k];
        float4 b = x4[k];
        float d0 = a.x - b.x;
        float d1 = a.y - b.y;
        float d2 = a.z - b.z;
        float d3 = a.w - b.w;
        acc = fmaf(d0, d0, acc);
        acc = fmaf(d1, d1, acc);
        acc = fmaf(d2, d2, acc);
        acc = fmaf(d3, d3, acc);
    }

    #pragma unroll
    for (int o = 16; o > 0; o >>= 1)
        acc += __shfl_xor_sync(0xFFFFFFFFu, acc, o);

    if (lane == 0) {
        float d = sqrtf(acc) + 0.001f;
        g_d[row] = d;
        int bits = __float_as_int(d);   // positive floats: int order == float order
        if (targets[row] == 1) {
            atomicAdd(&g_sp, (double)d);   // no return use -> REDG fire-and-forget
            atomicMin(&g_minpos, bits);
            atomicAdd(&g_np, 1);
        } else {
            atomicAdd(&g_sn, (double)d);
            atomicMax(&g_maxneg, bits);
        }
    }
    __syncthreads();

    __shared__ int s_last;
    if (tid == 0) {
        // Release-ordered ticket: publishes this block's writes (ordered
        // via the bar.sync above) without a MEMBAR.
        unsigned int one = 1u, t;
        asm volatile("atom.release.gpu.global.add.u32 %0, [%1], %2;"
                     : "=r"(t) : "l"(&g_ticket), "r"(one) : "memory");
        s_last = (t == NBLOCKS - 1);
    }
    __syncthreads();
    if (!s_last) return;

    // ================= last block: fused finalize =================
    asm volatile("fence.acq_rel.gpu;" ::: "memory");

    __shared__ float  posList[MAXLIST], negList[MAXLIST];
    __shared__ int    s_npl, s_nnl;
    __shared__ double redC[8];

    if (tid == 0) { s_npl = 0; s_nnl = 0; }
    __syncthreads();

    const float minpos = __int_as_float(g_minpos);
    const float maxneg = __int_as_float(g_maxneg);
    const float thrP = maxneg - MARGINF;   // pos matter if d_i < thrP
    const float thrN = minpos + MARGINF;   // neg matter if d_j > thrN

    // Scan (L2-hot): gather hinge-overflow candidates
    for (int k = tid; k < NROWS; k += DTHREADS) {
        int   t  = targets[k];
        float dv = g_d[k];
        if (t == 1) {
            if (dv < thrP) {
                int idx = atomicAdd(&s_npl, 1);
                if (idx < MAXLIST) posList[idx] = dv;
            }
        } else {
            if (dv > thrN) {
                int idx = atomicAdd(&s_nnl, 1);
                if (idx < MAXLIST) negList[idx] = dv;
            }
        }
    }
    __syncthreads();

    const int npl = min(s_npl, MAXLIST);
    const int nnl = min(s_nnl, MAXLIST);

    // Exact correction: pos-striped, neg list serial per pos
    float corrF = 0.0f;
    for (int ip = tid; ip < npl; ip += DTHREADS) {
        const float dp = posList[ip] + MARGINF;
        float a = 0.0f;
        for (int jn = 0; jn < nnl; jn++) {
            a += fmaxf(negList[jn] - dp, 0.0f);
        }
        corrF += a;
    }
    double corr = (double)corrF;
    #pragma unroll
    for (int o = 16; o > 0; o >>= 1)
        corr += __shfl_xor_sync(0xFFFFFFFFu, corr, o);
    if ((tid & 31) == 0) redC[tid >> 5] = corr;
    __syncthreads();

    if (tid == 0) {
        double c = 0.0;
        #pragma unroll
        for (int w = 0; w < 8; w++) c += redC[w];
        double Sp = g_sp, Sn = g_sn;
        int    p  = g_np;
        double Np = (double)p;
        double Nn = (double)(NROWS - p);
        double linear = Nn * Sp - Np * Sn + (double)MARGINF * Np * Nn;
        out[0] = (float)((linear + c) / (Np * Nn));
        // reset for next graph replay
        g_sp = 0.0;
        g_sn = 0.0;
        g_np = 0;
        g_minpos = 0x7f800000;
        g_maxneg = 0;
        g_ticket = 0u;
    }
}

extern "C" void kernel_launch(void* const* d_in, const int* in_sizes, int n_in,
                              void* d_out, int out_size)
{
    const float* recon   = (const float*)d_in[0];
    const float* x       = (const float*)d_in[1];
    const int*   targets = (const int*)d_in[2];
    float* out = (float*)d_out;

    dist_kernel<<<NBLOCKS, DTHREADS>>>(recon, x, targets, out);
}

// round 15
// speedup vs baseline: 1.0555x; 1.0245x over previous
#include <cuda_runtime.h>

#define NROWS  8192
#define DCOLS  4096
#define MARGINF 5.0f
#define MAXLIST 2048
#define FBLOCKS 64
#define RPB_F   (NROWS / FBLOCKS)   // 128 rows per finalize block
#define FTHREADS 256

// Scratch. Initial values match the post-run reset done by the last block,
// so every graph replay starts from identical state.
__device__ float        g_d[NROWS];
__device__ double       g_sp = 0.0;             // sum of pos distances
__device__ double       g_sn = 0.0;             // sum of neg distances
__device__ int          g_np = 0;               // pos count
__device__ int          g_minpos = 0x7f800000;  // +inf bits (pos-float ordering)
__device__ int          g_maxneg = 0;           // 0.0f bits
__device__ unsigned int g_ticket = 0u;

// Pure HBM-bound distance kernel (no atomics, no ticket — runs at LTS cap).
// One block per row: d = sqrt(sum (recon-x)^2) + 0.001.
__global__ __launch_bounds__(256) void dist_kernel(
    const float* __restrict__ recon, const float* __restrict__ x)
{
    const int row = blockIdx.x;
    const float4* r4 = reinterpret_cast<const float4*>(recon + (size_t)row * DCOLS);
    const float4* x4 = reinterpret_cast<const float4*>(x + (size_t)row * DCOLS);

    float acc = 0.0f;
    #pragma unroll 4
    for (int k = threadIdx.x; k < DCOLS / 4; k += 256) {
        float4 a = r4[k];
        float4 b = x4[k];
        float d0 = a.x - b.x;
        float d1 = a.y - b.y;
        float d2 = a.z - b.z;
        float d3 = a.w - b.w;
        acc = fmaf(d0, d0, acc);
        acc = fmaf(d1, d1, acc);
        acc = fmaf(d2, d2, acc);
        acc = fmaf(d3, d3, acc);
    }

    #pragma unroll
    for (int o = 16; o > 0; o >>= 1)
        acc += __shfl_xor_sync(0xFFFFFFFFu, acc, o);

    __shared__ float ws[8];
    if ((threadIdx.x & 31) == 0) ws[threadIdx.x >> 5] = acc;
    __syncthreads();
    if (threadIdx.x == 0) {
        float s = 0.0f;
        #pragma unroll
        for (int w = 0; w < 8; w++) s += ws[w];
        g_d[row] = sqrtf(s) + 0.001f;
    }
}

// Multi-block finalize.
//   Sum_{i pos, j neg} max(0, d_i - d_j + M)
// = [Nn*Sp - Np*Sn + M*Np*Nn] + Sum max(0, d_j - d_i - M)
// Phase 1 (all 64 blocks): partial stats over a 128-row slice, REDG to
// globals (64 ops/address — no serialization pressure), release-ticket.
// Phase 2 (last block): acquire, thresholds, rescan all rows (L2-hot) to
// gather the ~330 hinge-overflow candidates, exact pos-striped correction,
// write output, reset globals for the next graph replay.
__global__ __launch_bounds__(FTHREADS) void final_kernel(
    const int* __restrict__ targets, float* __restrict__ out)
{
    const int tid  = threadIdx.x;
    const int lane = tid & 31;
    const int wid  = tid >> 5;

    // ---- Phase 1: slice stats ----
    double sp = 0.0, sn = 0.0;
    float  mnp = 1.0e30f, mxn = -1.0e30f;
    int np = 0;
    const int base = blockIdx.x * RPB_F;
    for (int k = base + tid; k < base + RPB_F; k += FTHREADS) {
        int   t  = targets[k];
        float dv = g_d[k];
        if (t == 1) {
            sp += (double)dv;
            mnp = fminf(mnp, dv);
            np++;
        } else {
            sn += (double)dv;
            mxn = fmaxf(mxn, dv);
        }
    }
    #pragma unroll
    for (int o = 16; o > 0; o >>= 1) {
        sp  += __shfl_xor_sync(0xFFFFFFFFu, sp, o);
        sn  += __shfl_xor_sync(0xFFFFFFFFu, sn, o);
        mnp  = fminf(mnp, __shfl_xor_sync(0xFFFFFFFFu, mnp, o));
        mxn  = fmaxf(mxn, __shfl_xor_sync(0xFFFFFFFFu, mxn, o));
        np  += __shfl_xor_sync(0xFFFFFFFFu, np, o);
    }
    __shared__ double rSp[8], rSn[8];
    __shared__ float  rMn[8], rMx[8];
    __shared__ int    rNp[8];
    if (lane == 0) {
        rSp[wid] = sp; rSn[wid] = sn;
        rMn[wid] = mnp; rMx[wid] = mxn; rNp[wid] = np;
    }
    __syncthreads();

    __shared__ int s_last;
    if (tid == 0) {
        double bsp = 0.0, bsn = 0.0;
        float  bmn = 1.0e30f, bmx = -1.0e30f;
        int bnp = 0;
        #pragma unroll
        for (int w = 0; w < 8; w++) {
            bsp += rSp[w]; bsn += rSn[w];
            bmn = fminf(bmn, rMn[w]); bmx = fmaxf(bmx, rMx[w]);
            bnp += rNp[w];
        }
        atomicAdd(&g_sp, bsp);
        atomicAdd(&g_sn, bsn);
        atomicAdd(&g_np, bnp);
        if (bmn < 1.0e29f)  atomicMin(&g_minpos, __float_as_int(bmn));
        if (bmx > -1.0e29f) atomicMax(&g_maxneg, __float_as_int(bmx));
        unsigned int one = 1u, t;
        asm volatile("atom.release.gpu.global.add.u32 %0, [%1], %2;"
                     : "=r"(t) : "l"(&g_ticket), "r"(one) : "memory");
        s_last = (t == FBLOCKS - 1);
    }
    __syncthreads();
    if (!s_last) return;

    // ---- Phase 2: last block ----
    asm volatile("fence.acq_rel.gpu;" ::: "memory");

    __shared__ float  posList[MAXLIST], negList[MAXLIST];
    __shared__ int    s_npl, s_nnl;
    __shared__ double redC[8];

    if (tid == 0) { s_npl = 0; s_nnl = 0; }
    __syncthreads();

    const float minpos = __int_as_float(g_minpos);
    const float maxneg = __int_as_float(g_maxneg);
    const float thrP = maxneg - MARGINF;   // pos matter if d_i < thrP
    const float thrN = minpos + MARGINF;   // neg matter if d_j > thrN

    for (int k = tid; k < NROWS; k += FTHREADS) {
        int   t  = targets[k];
        float dv = g_d[k];
        if (t == 1) {
            if (dv < thrP) {
                int idx = atomicAdd(&s_npl, 1);
                if (idx < MAXLIST) posList[idx] = dv;
            }
        } else {
            if (dv > thrN) {
                int idx = atomicAdd(&s_nnl, 1);
                if (idx < MAXLIST) negList[idx] = dv;
            }
        }
    }
    __syncthreads();

    const int npl = min(s_npl, MAXLIST);
    const int nnl = min(s_nnl, MAXLIST);

    // Exact correction: pos-striped, neg list serial per pos
    float corrF = 0.0f;
    for (int ip = tid; ip < npl; ip += FTHREADS) {
        const float dp = posList[ip] + MARGINF;
        float a = 0.0f;
        for (int jn = 0; jn < nnl; jn++) {
            a += fmaxf(negList[jn] - dp, 0.0f);
        }
        corrF += a;
    }
    double corr = (double)corrF;
    #pragma unroll
    for (int o = 16; o > 0; o >>= 1)
        corr += __shfl_xor_sync(0xFFFFFFFFu, corr, o);
    if (lane == 0) redC[wid] = corr;
    __syncthreads();

    if (tid == 0) {
        double c = 0.0;
        #pragma unroll
        for (int w = 0; w < 8; w++) c += redC[w];
        double Sp = g_sp, Sn = g_sn;
        int    p  = g_np;
        double Np = (double)p;
        double Nn = (double)(NROWS - p);
        double linear = Nn * Sp - Np * Sn + (double)MARGINF * Np * Nn;
        out[0] = (float)((linear + c) / (Np * Nn));
        // reset for next graph replay
        g_sp = 0.0;
        g_sn = 0.0;
        g_np = 0;
        g_minpos = 0x7f800000;
        g_maxneg = 0;
        g_ticket = 0u;
    }
}

extern "C" void kernel_launch(void* const* d_in, const int* in_sizes, int n_in,
                              void* d_out, int out_size)
{
    const float* recon   = (const float*)d_in[0];
    const float* x       = (const float*)d_in[1];
    const int*   targets = (const int*)d_in[2];
    float* out = (float*)d_out;

    dist_kernel<<<NROWS, 256>>>(recon, x);
    final_kernel<<<FBLOCKS, FTHREADS>>>(targets, out);
}